// round 12
// baseline (speedup 1.0000x reference)
#include <cuda_runtime.h>
#include <cstdint>
#include <cstddef>

// Fixed shapes: n=512, H=512, B=256
#define BB 256
#define HH 512
#define NN 512
#define GBLK 128      // 8 row-groups (jy) x 16 col tiles (jx); 1 block/SM
#define NTHR 128      // 4 warps: thread = 2 rows x 4 cols of a 32x32 tile
#define KT   32
#define SAD  66       // dup-act smem stride per k (64 payload + 2 pad)
#define SW   36       // weight smem stride per k (32 cols + 4 pad, 16B-aligned)
#define OAX  0
#define OAH  2112
#define OW(g) (4224 + (g) * 1152)
#define STG  11136    // floats per stage
#define SMEMF (2 * STG)
#define NEG_INF (-1.0e9f)
#define F32_TINY 1.17549435e-38f

// -------- device scratch (no allocations allowed) --------
__device__ float    g_h0[2][BB * HH];
__device__ float    g_h1[2][BB * HH];
__device__ float    g_logits[BB * NN];
__device__ int      g_sel[BB];
__device__ unsigned g_avail[BB * (NN / 32)];
__device__ float    g_lp[BB];
__device__ float    g_rowsum[3 * HH];
__device__ unsigned g_bar_cnt;      // global (init only)
__device__ unsigned g_bar_gen;
__device__ unsigned g_grp_cnt[8];   // per-group barriers
__device__ unsigned g_grp_gen[8];

// -------- Threefry-2x32 (20 rounds), bit-exact JAX replica --------
__device__ __forceinline__ unsigned rotl32(unsigned v, int r) {
    return (v << r) | (v >> (32 - r));
}

__device__ __forceinline__ void tf2x32(unsigned ks0, unsigned ks1,
                                       unsigned x0, unsigned x1,
                                       unsigned& o0, unsigned& o1)
{
    unsigned ks2 = ks0 ^ ks1 ^ 0x1BD11BDAu;
    x0 += ks0; x1 += ks1;
#define TF_R4(a,b,c,d) \
    x0 += x1; x1 = rotl32(x1,(a)); x1 ^= x0; \
    x0 += x1; x1 = rotl32(x1,(b)); x1 ^= x0; \
    x0 += x1; x1 = rotl32(x1,(c)); x1 ^= x0; \
    x0 += x1; x1 = rotl32(x1,(d)); x1 ^= x0;
    TF_R4(13,15,26,6)   x0 += ks1; x1 += ks2 + 1u;
    TF_R4(17,29,16,24)  x0 += ks2; x1 += ks0 + 2u;
    TF_R4(13,15,26,6)   x0 += ks0; x1 += ks1 + 3u;
    TF_R4(17,29,16,24)  x0 += ks1; x1 += ks2 + 4u;
    TF_R4(13,15,26,6)   x0 += ks2; x1 += ks0 + 5u;
#undef TF_R4
    o0 = x0; o1 = x1;
}

// XLA lowers logistic(x) as 0.5 + 0.5*tanh(0.5*x); mirror that op graph.
__device__ __forceinline__ float jax_sigmoid(float x) {
    return __fadd_rn(0.5f, __fmul_rn(0.5f, tanhf(__fmul_rn(0.5f, x))));
}

__device__ __forceinline__ float4 ldcg4(const float* p) {
    return __ldcg(reinterpret_cast<const float4*>(p));
}
__device__ __forceinline__ float4 ldg4(const float* p) {
    return __ldg(reinterpret_cast<const float4*>(p));
}
__device__ __forceinline__ float f4c(float4 v, int i) {
    return i == 0 ? v.x : i == 1 ? v.y : i == 2 ? v.z : v.w;
}

// -------- packed f32x2 FMA: two IEEE fp32 FMAs per instruction --------
union f2u { float2 f; unsigned long long u; };

__device__ __forceinline__ float2 ffma2(float2 a, float2 b, float2 c) {
    f2u A, B, C, D;
    A.f = a; B.f = b; C.f = c;
    asm("fma.rn.f32x2 %0, %1, %2, %3;" : "=l"(D.u) : "l"(A.u), "l"(B.u), "l"(C.u));
    return D.f;
}
__device__ __forceinline__ float2 f2lo(float4 v) { return make_float2(v.x, v.y); }
__device__ __forceinline__ float2 f2hi(float4 v) { return make_float2(v.z, v.w); }
__device__ __forceinline__ float2 lds2(const float* p) {
    return *reinterpret_cast<const float2*>(p);
}
__device__ __forceinline__ float4 ld4s(const float* p) {
    return *reinterpret_cast<const float4*>(p);
}
__device__ __forceinline__ void st2d(float* p, float v) {
    *reinterpret_cast<float2*>(p) = make_float2(v, v);
}

// store one float4 (4 consecutive k of row r) duplicated into act buffer
#define ST_ACT(basep, ko, vv, rr) do { \
    st2d((basep) + ((ko) + 0) * SAD + 2 * (rr), (vv).x); \
    st2d((basep) + ((ko) + 1) * SAD + 2 * (rr), (vv).y); \
    st2d((basep) + ((ko) + 2) * SAD + 2 * (rr), (vv).z); \
    st2d((basep) + ((ko) + 3) * SAD + 2 * (rr), (vv).w); \
} while (0)
// store one float4 (4 consecutive k of col c) into weight buffer
#define ST_W(basep, ko, vv, cc) do { \
    (basep)[((ko) + 0) * SW + (cc)] = (vv).x; \
    (basep)[((ko) + 1) * SW + (cc)] = (vv).y; \
    (basep)[((ko) + 2) * SW + (cc)] = (vv).z; \
    (basep)[((ko) + 3) * SW + (cc)] = (vv).w; \
} while (0)

// -------- barriers --------
__device__ __forceinline__ void gsync_all() {
    __syncthreads();
    if (threadIdx.x == 0) {
        __threadfence();
        unsigned gen = *(volatile unsigned*)&g_bar_gen;
        if (atomicAdd(&g_bar_cnt, 1u) == GBLK - 1u) {
            atomicExch(&g_bar_cnt, 0u);
            __threadfence();
            atomicAdd(&g_bar_gen, 1u);
        } else {
            while (*(volatile unsigned*)&g_bar_gen == gen) { }
        }
        __threadfence();
    }
    __syncthreads();
}

__device__ __forceinline__ void gsync_grp(int gid) {
    __syncthreads();
    if (threadIdx.x == 0) {
        __threadfence();
        unsigned gen = *(volatile unsigned*)&g_grp_gen[gid];
        if (atomicAdd(&g_grp_cnt[gid], 1u) == 15u) {
            atomicExch(&g_grp_cnt[gid], 0u);
            __threadfence();
            atomicAdd(&g_grp_gen[gid], 1u);
        } else {
            while (*(volatile unsigned*)&g_grp_gen[gid] == gen) { }
        }
        __threadfence();
    }
    __syncthreads();
}

__global__ void __launch_bounds__(NTHR, 1) perm_persistent(
    const float* __restrict__ Wih0, const float* __restrict__ Whh0,
    const float* __restrict__ bih0, const float* __restrict__ bhh0,
    const float* __restrict__ Wih1, const float* __restrict__ Whh1,
    const float* __restrict__ bih1, const float* __restrict__ bhh1,
    const float* __restrict__ Wout, const float* __restrict__ bout,
    float* __restrict__ out)
{
    extern __shared__ __align__(16) float SM[];   // 2 stages x STG floats

    const int blk = blockIdx.x;
    const int tid = threadIdx.x;

    // ---------------- init (per-launch state reset) ----------------
    {
        for (int i = blk * NTHR + tid; i < BB * HH; i += GBLK * NTHR) {
            g_h0[0][i] = 0.0f;
            g_h1[0][i] = 0.0f;
        }
        if (tid < 2) g_lp[2 * blk + tid] = 0.0f;
        if (tid < 32) g_avail[(2 * blk + (tid >> 4)) * 16 + (tid & 15)] = 0xFFFFFFFFu;
        int lane = tid & 31;
        for (int row = blk * 4 + (tid >> 5); row < 3 * HH; row += GBLK * 4) {
            const float* rp = Wih0 + (size_t)row * HH;
            float s = 0.0f;
            for (int k = lane; k < HH; k += 32) s = __fadd_rn(s, rp[k]);
#pragma unroll
            for (int off = 16; off > 0; off >>= 1)
                s = __fadd_rn(s, __shfl_xor_sync(0xFFFFFFFFu, s, off));
            if (lane == 0) g_rowsum[row] = s;
        }
    }
    gsync_all();

    // tiles: blk = jy*16 + jx; group gid = jy (16 blocks each, closed rows)
    const int jx = blk & 15, jy = blk >> 4;
    const int gid = jy;
    const int bm0 = jy * 32, jn0 = jx * 32;
    const int tx = tid & 7;          // col group: 4tx .. 4tx+3
    const int ty = tid >> 3;         // rows 2ty, 2ty+1  (ty 0..15)
    const int ldr = tid >> 2;        // loader row/col 0..31
    const int kq  = (tid & 3) << 2;  // loader k offsets {kq, kq+16}

    for (int t = 0; t < NN; t++) {
        const int p = t & 1;
        const float* h0_in  = g_h0[p];
        float*       h0_out = g_h0[p ^ 1];
        const float* h1_in  = g_h1[p];
        float*       h1_out = g_h1[p ^ 1];

        // ================ layer 0: h0n = GRU(onehot(sel), h0) ================
        {
            float gi[2][3][4];
            if (t == 0) {
#pragma unroll
                for (int g = 0; g < 3; g++)
#pragma unroll
                    for (int c = 0; c < 4; c++) {
                        float v = __ldcg(&g_rowsum[g * HH + jn0 + 4 * tx + c]);
                        gi[0][g][c] = v; gi[1][g][c] = v;
                    }
            } else {
#pragma unroll
                for (int mi = 0; mi < 2; mi++) {
                    int xs = __ldcg(&g_sel[bm0 + 2 * ty + mi]);
#pragma unroll
                    for (int g = 0; g < 3; g++)
#pragma unroll
                        for (int c = 0; c < 4; c++)
                            gi[mi][g][c] = __ldg(&Wih0[(size_t)(g * HH + jn0 + 4 * tx + c) * HH + xs]);
                }
            }

            float2 acc[3][2][2];   // [gate][row mi][col half]
#pragma unroll
            for (int g = 0; g < 3; g++)
#pragma unroll
                for (int mi = 0; mi < 2; mi++) {
                    acc[g][mi][0] = make_float2(0.f, 0.f);
                    acc[g][mi][1] = make_float2(0.f, 0.f);
                }

            const float* asrc = h0_in + (size_t)(bm0 + ldr) * HH + kq;
            const float* wsrc[3];
#pragma unroll
            for (int g = 0; g < 3; g++)
                wsrc[g] = Whh0 + (size_t)(g * HH + jn0 + ldr) * HH + kq;

            float4 ax0 = ldcg4(asrc), ax1 = ldcg4(asrc + 16);
            float4 wa[3], wb[3];
#pragma unroll
            for (int g = 0; g < 3; g++) { wa[g] = ldg4(wsrc[g]); wb[g] = ldg4(wsrc[g] + 16); }
            {
                float* B = SM;
                ST_ACT(B + OAX, kq, ax0, ldr); ST_ACT(B + OAX, kq + 16, ax1, ldr);
#pragma unroll
                for (int g = 0; g < 3; g++) {
                    ST_W(B + OW(g), kq, wa[g], ldr); ST_W(B + OW(g), kq + 16, wb[g], ldr);
                }
            }
            __syncthreads();

#pragma unroll 1
            for (int tl = 0; tl < 16; tl++) {
                float* BC = SM + (tl & 1) * STG;
                float* BN = SM + ((tl & 1) ^ 1) * STG;
                if (tl < 15) {
                    int kn = (tl + 1) * KT;
                    ax0 = ldcg4(asrc + kn); ax1 = ldcg4(asrc + kn + 16);
#pragma unroll
                    for (int g = 0; g < 3; g++) { wa[g] = ldg4(wsrc[g] + kn); wb[g] = ldg4(wsrc[g] + kn + 16); }
                }
                const float* A = BC + OAX;
#pragma unroll
                for (int k = 0; k < KT; k++) {
                    float2 xa0 = lds2(A + k * SAD + 4 * ty);        // (a,a) row 2ty
                    float2 xa1 = lds2(A + k * SAD + 4 * ty + 2);    // (a,a) row 2ty+1
#pragma unroll
                    for (int g = 0; g < 3; g++) {
                        float4 w = ld4s(BC + OW(g) + k * SW + 4 * tx);
                        float2 wl = f2lo(w), wh = f2hi(w);
                        acc[g][0][0] = ffma2(xa0, wl, acc[g][0][0]);
                        acc[g][0][1] = ffma2(xa0, wh, acc[g][0][1]);
                        acc[g][1][0] = ffma2(xa1, wl, acc[g][1][0]);
                        acc[g][1][1] = ffma2(xa1, wh, acc[g][1][1]);
                    }
                }
                if (tl < 15) {
                    ST_ACT(BN + OAX, kq, ax0, ldr); ST_ACT(BN + OAX, kq + 16, ax1, ldr);
#pragma unroll
                    for (int g = 0; g < 3; g++) {
                        ST_W(BN + OW(g), kq, wa[g], ldr); ST_W(BN + OW(g), kq + 16, wb[g], ldr);
                    }
                }
                __syncthreads();
            }

            float4 bi0 = ldg4(bih0 + jn0 + 4 * tx);
            float4 bi1 = ldg4(bih0 + HH + jn0 + 4 * tx);
            float4 bi2 = ldg4(bih0 + 2 * HH + jn0 + 4 * tx);
            float4 bh0 = ldg4(bhh0 + jn0 + 4 * tx);
            float4 bh1 = ldg4(bhh0 + HH + jn0 + 4 * tx);
            float4 bh2 = ldg4(bhh0 + 2 * HH + jn0 + 4 * tx);
#pragma unroll
            for (int mi = 0; mi < 2; mi++) {
                int b = bm0 + 2 * ty + mi;
                float4 hp4 = ldcg4(h0_in + (size_t)b * HH + jn0 + 4 * tx);
                float res[4];
#pragma unroll
                for (int c = 0; c < 4; c++) {
                    float ar_ = (c & 1) ? acc[0][mi][c >> 1].y : acc[0][mi][c >> 1].x;
                    float az_ = (c & 1) ? acc[1][mi][c >> 1].y : acc[1][mi][c >> 1].x;
                    float an_ = (c & 1) ? acc[2][mi][c >> 1].y : acc[2][mi][c >> 1].x;
                    float ir  = __fadd_rn(gi[mi][0][c], f4c(bi0, c));
                    float iz  = __fadd_rn(gi[mi][1][c], f4c(bi1, c));
                    float inn = __fadd_rn(gi[mi][2][c], f4c(bi2, c));
                    float hr  = __fadd_rn(ar_, f4c(bh0, c));
                    float hz  = __fadd_rn(az_, f4c(bh1, c));
                    float hn  = __fadd_rn(an_, f4c(bh2, c));
                    float r  = jax_sigmoid(__fadd_rn(ir, hr));
                    float z  = jax_sigmoid(__fadd_rn(iz, hz));
                    float ng = tanhf(__fadd_rn(inn, __fmul_rn(r, hn)));
                    float hp = f4c(hp4, c);
                    res[c] = __fadd_rn(__fmul_rn(__fsub_rn(1.0f, z), ng), __fmul_rn(z, hp));
                }
                *reinterpret_cast<float4*>(h0_out + (size_t)b * HH + jn0 + 4 * tx) =
                    make_float4(res[0], res[1], res[2], res[3]);
            }
        }
        gsync_grp(gid);

        // ================ layer 1: h1n = GRU(h0n, h1) ================
        {
            float2 accI[3][2][2], accH[3][2][2];
#pragma unroll
            for (int g = 0; g < 3; g++)
#pragma unroll
                for (int mi = 0; mi < 2; mi++) {
                    accI[g][mi][0] = make_float2(0.f, 0.f); accI[g][mi][1] = make_float2(0.f, 0.f);
                    accH[g][mi][0] = make_float2(0.f, 0.f); accH[g][mi][1] = make_float2(0.f, 0.f);
                }

            const float* xsrc = h0_out + (size_t)(bm0 + ldr) * HH + kq;
            const float* hsrc = h1_in  + (size_t)(bm0 + ldr) * HH + kq;
            const float* wsrc[6];
#pragma unroll
            for (int g = 0; g < 3; g++) {
                wsrc[g]     = Wih1 + (size_t)(g * HH + jn0 + ldr) * HH + kq;
                wsrc[3 + g] = Whh1 + (size_t)(g * HH + jn0 + ldr) * HH + kq;
            }

            float4 ax0 = ldcg4(xsrc), ax1 = ldcg4(xsrc + 16);
            float4 ah0 = ldcg4(hsrc), ah1 = ldcg4(hsrc + 16);
            float4 wa[6], wb[6];
#pragma unroll
            for (int g = 0; g < 6; g++) { wa[g] = ldg4(wsrc[g]); wb[g] = ldg4(wsrc[g] + 16); }
            {
                float* B = SM;
                ST_ACT(B + OAX, kq, ax0, ldr); ST_ACT(B + OAX, kq + 16, ax1, ldr);
                ST_ACT(B + OAH, kq, ah0, ldr); ST_ACT(B + OAH, kq + 16, ah1, ldr);
#pragma unroll
                for (int g = 0; g < 6; g++) {
                    ST_W(B + OW(g), kq, wa[g], ldr); ST_W(B + OW(g), kq + 16, wb[g], ldr);
                }
            }
            __syncthreads();

#pragma unroll 1
            for (int tl = 0; tl < 16; tl++) {
                float* BC = SM + (tl & 1) * STG;
                float* BN = SM + ((tl & 1) ^ 1) * STG;
                if (tl < 15) {
                    int kn = (tl + 1) * KT;
                    ax0 = ldcg4(xsrc + kn); ax1 = ldcg4(xsrc + kn + 16);
                    ah0 = ldcg4(hsrc + kn); ah1 = ldcg4(hsrc + kn + 16);
#pragma unroll
                    for (int g = 0; g < 6; g++) { wa[g] = ldg4(wsrc[g] + kn); wb[g] = ldg4(wsrc[g] + kn + 16); }
                }
                const float* AX = BC + OAX;
                const float* AH = BC + OAH;
#pragma unroll
                for (int k = 0; k < KT; k++) {
                    float2 xa0 = lds2(AX + k * SAD + 4 * ty);
                    float2 xa1 = lds2(AX + k * SAD + 4 * ty + 2);
                    float2 ha0 = lds2(AH + k * SAD + 4 * ty);
                    float2 ha1 = lds2(AH + k * SAD + 4 * ty + 2);
#pragma unroll
                    for (int g = 0; g < 3; g++) {
                        float4 wi = ld4s(BC + OW(g) + k * SW + 4 * tx);
                        float2 il = f2lo(wi), ih = f2hi(wi);
                        accI[g][0][0] = ffma2(xa0, il, accI[g][0][0]);
                        accI[g][0][1] = ffma2(xa0, ih, accI[g][0][1]);
                        accI[g][1][0] = ffma2(xa1, il, accI[g][1][0]);
                        accI[g][1][1] = ffma2(xa1, ih, accI[g][1][1]);
                        float4 wh = ld4s(BC + OW(3 + g) + k * SW + 4 * tx);
                        float2 hl = f2lo(wh), hh = f2hi(wh);
                        accH[g][0][0] = ffma2(ha0, hl, accH[g][0][0]);
                        accH[g][0][1] = ffma2(ha0, hh, accH[g][0][1]);
                        accH[g][1][0] = ffma2(ha1, hl, accH[g][1][0]);
                        accH[g][1][1] = ffma2(ha1, hh, accH[g][1][1]);
                    }
                }
                if (tl < 15) {
                    ST_ACT(BN + OAX, kq, ax0, ldr); ST_ACT(BN + OAX, kq + 16, ax1, ldr);
                    ST_ACT(BN + OAH, kq, ah0, ldr); ST_ACT(BN + OAH, kq + 16, ah1, ldr);
#pragma unroll
                    for (int g = 0; g < 6; g++) {
                        ST_W(BN + OW(g), kq, wa[g], ldr); ST_W(BN + OW(g), kq + 16, wb[g], ldr);
                    }
                }
                __syncthreads();
            }

            float4 bi0 = ldg4(bih1 + jn0 + 4 * tx);
            float4 bi1 = ldg4(bih1 + HH + jn0 + 4 * tx);
            float4 bi2 = ldg4(bih1 + 2 * HH + jn0 + 4 * tx);
            float4 bh0 = ldg4(bhh1 + jn0 + 4 * tx);
            float4 bh1 = ldg4(bhh1 + HH + jn0 + 4 * tx);
            float4 bh2 = ldg4(bhh1 + 2 * HH + jn0 + 4 * tx);
#pragma unroll
            for (int mi = 0; mi < 2; mi++) {
                int b = bm0 + 2 * ty + mi;
                float4 hp4 = ldcg4(h1_in + (size_t)b * HH + jn0 + 4 * tx);
                float res[4];
#pragma unroll
                for (int c = 0; c < 4; c++) {
                    float aIr = (c & 1) ? accI[0][mi][c >> 1].y : accI[0][mi][c >> 1].x;
                    float aIz = (c & 1) ? accI[1][mi][c >> 1].y : accI[1][mi][c >> 1].x;
                    float aIn = (c & 1) ? accI[2][mi][c >> 1].y : accI[2][mi][c >> 1].x;
                    float aHr = (c & 1) ? accH[0][mi][c >> 1].y : accH[0][mi][c >> 1].x;
                    float aHz = (c & 1) ? accH[1][mi][c >> 1].y : accH[1][mi][c >> 1].x;
                    float aHn = (c & 1) ? accH[2][mi][c >> 1].y : accH[2][mi][c >> 1].x;
                    float ir  = __fadd_rn(aIr, f4c(bi0, c));
                    float iz  = __fadd_rn(aIz, f4c(bi1, c));
                    float inn = __fadd_rn(aIn, f4c(bi2, c));
                    float hr  = __fadd_rn(aHr, f4c(bh0, c));
                    float hz  = __fadd_rn(aHz, f4c(bh1, c));
                    float hn  = __fadd_rn(aHn, f4c(bh2, c));
                    float r  = jax_sigmoid(__fadd_rn(ir, hr));
                    float z  = jax_sigmoid(__fadd_rn(iz, hz));
                    float ng = tanhf(__fadd_rn(inn, __fmul_rn(r, hn)));
                    float hp = f4c(hp4, c);
                    res[c] = __fadd_rn(__fmul_rn(__fsub_rn(1.0f, z), ng), __fmul_rn(z, hp));
                }
                *reinterpret_cast<float4*>(h1_out + (size_t)b * HH + jn0 + 4 * tx) =
                    make_float4(res[0], res[1], res[2], res[3]);
            }
        }
        gsync_grp(gid);

        // ================ logits = h1n @ W_out^T + b_out ================
        {
            float2 acc[2][2];
#pragma unroll
            for (int mi = 0; mi < 2; mi++) { acc[mi][0] = make_float2(0.f,0.f); acc[mi][1] = make_float2(0.f,0.f); }

            const float* asrc = h1_out + (size_t)(bm0 + ldr) * HH + kq;
            const float* wsrc = Wout + (size_t)(jn0 + ldr) * HH + kq;

            float4 ax0 = ldcg4(asrc), ax1 = ldcg4(asrc + 16);
            float4 wa = ldg4(wsrc), wb = ldg4(wsrc + 16);
            {
                float* B = SM;
                ST_ACT(B + OAX, kq, ax0, ldr); ST_ACT(B + OAX, kq + 16, ax1, ldr);
                ST_W(B + OW(0), kq, wa, ldr);  ST_W(B + OW(0), kq + 16, wb, ldr);
            }
            __syncthreads();

#pragma unroll 1
            for (int tl = 0; tl < 16; tl++) {
                float* BC = SM + (tl & 1) * STG;
                float* BN = SM + ((tl & 1) ^ 1) * STG;
                if (tl < 15) {
                    int kn = (tl + 1) * KT;
                    ax0 = ldcg4(asrc + kn); ax1 = ldcg4(asrc + kn + 16);
                    wa = ldg4(wsrc + kn);   wb = ldg4(wsrc + kn + 16);
                }
                const float* A = BC + OAX;
#pragma unroll
                for (int k = 0; k < KT; k++) {
                    float2 xa0 = lds2(A + k * SAD + 4 * ty);
                    float2 xa1 = lds2(A + k * SAD + 4 * ty + 2);
                    float4 w = ld4s(BC + OW(0) + k * SW + 4 * tx);
                    float2 wl = f2lo(w), wh = f2hi(w);
                    acc[0][0] = ffma2(xa0, wl, acc[0][0]);
                    acc[0][1] = ffma2(xa0, wh, acc[0][1]);
                    acc[1][0] = ffma2(xa1, wl, acc[1][0]);
                    acc[1][1] = ffma2(xa1, wh, acc[1][1]);
                }
                if (tl < 15) {
                    ST_ACT(BN + OAX, kq, ax0, ldr); ST_ACT(BN + OAX, kq + 16, ax1, ldr);
                    ST_W(BN + OW(0), kq, wa, ldr);  ST_W(BN + OW(0), kq + 16, wb, ldr);
                }
                __syncthreads();
            }

            float4 bo = ldg4(bout + jn0 + 4 * tx);
#pragma unroll
            for (int mi = 0; mi < 2; mi++) {
                int b = bm0 + 2 * ty + mi;
                float res[4];
#pragma unroll
                for (int c = 0; c < 4; c++) {
                    float a = (c & 1) ? acc[mi][c >> 1].y : acc[mi][c >> 1].x;
                    res[c] = __fadd_rn(a, f4c(bo, c));
                }
                *reinterpret_cast<float4*>(g_logits + (size_t)b * NN + jn0 + 4 * tx) =
                    make_float4(res[0], res[1], res[2], res[3]);
            }
        }
        gsync_grp(gid);

        // ===== sample: rows 2*blk, 2*blk+1 (64 threads each), shuffle reductions =====
        {
            float* SSv = SM;                  // [2][2]
            int*   SSi = (int*)(SM + 4);      // [2][2]
            float* SVm = SM + 8;              // [2][2]
            float* SEx = SM + 12;             // [2][2]

            const int r   = tid >> 6;         // row within block pair
            const int c0  = tid & 63;
            const int wir = (tid >> 5) & 1;   // warp within row
            const int b   = 2 * blk + r;

            unsigned sk0, sk1;
            tf2x32(0u, 42u, 0u, (unsigned)t, sk0, sk1);

            float vq[8];
            float bs = -3.4e38f; int bi = 0;
            float lv = -3.4e38f;
#pragma unroll
            for (int q = 0; q < 8; q++) {
                int col = c0 + 64 * q;
                float lg = __ldcg(&g_logits[(size_t)b * NN + col]);
                unsigned w = g_avail[b * 16 + (col >> 5)];
                float v = ((w >> (col & 31)) & 1u) ? lg : NEG_INF;
                vq[q] = v;
                unsigned o0, o1;
                tf2x32(sk0, sk1, 0u, (unsigned)(b * NN + col), o0, o1);
                unsigned bits = o0 ^ o1;
                float f = __fsub_rn(__uint_as_float((bits >> 9) | 0x3F800000u), 1.0f);
                float gmb = -logf(-logf(fmaxf(f, F32_TINY)));
                float s = __fadd_rn(gmb, v);
                if (s > bs || (s == bs && col < bi)) { bs = s; bi = col; }
                lv = fmaxf(lv, v);
            }
#pragma unroll
            for (int off = 16; off > 0; off >>= 1) {
                float os = __shfl_xor_sync(0xFFFFFFFFu, bs, off);
                int   oi = __shfl_xor_sync(0xFFFFFFFFu, bi, off);
                float ov = __shfl_xor_sync(0xFFFFFFFFu, lv, off);
                if (os > bs || (os == bs && oi < bi)) { bs = os; bi = oi; }
                lv = fmaxf(lv, ov);
            }
            if ((tid & 31) == 0) {
                SSv[r * 2 + wir] = bs; SSi[r * 2 + wir] = bi; SVm[r * 2 + wir] = lv;
            }
            __syncthreads();

            float vmax = fmaxf(SVm[r * 2], SVm[r * 2 + 1]);

            float es = 0.0f;
#pragma unroll
            for (int q = 0; q < 8; q++)
                es = __fadd_rn(es, expf(__fsub_rn(vq[q], vmax)));
#pragma unroll
            for (int off = 16; off > 0; off >>= 1)
                es = __fadd_rn(es, __shfl_xor_sync(0xFFFFFFFFu, es, off));
            if ((tid & 31) == 0) SEx[r * 2 + wir] = es;
            __syncthreads();

            if (c0 == 0) {
                float fs = SSv[r * 2]; int fi = SSi[r * 2];
                {
                    float os = SSv[r * 2 + 1]; int oi = SSi[r * 2 + 1];
                    if (os > fs || (os == fs && oi < fi)) { fs = os; fi = oi; }
                }
                float S = __fadd_rn(SEx[r * 2], SEx[r * 2 + 1]);
                int idx = fi;
                float vsel = __ldcg(&g_logits[(size_t)b * NN + idx]);   // idx is available
                float ps = __fdiv_rn(expf(__fsub_rn(vsel, vmax)), S);
                float lp = __fadd_rn(g_lp[b], logf(__fadd_rn(ps, 1e-9f)));
                g_lp[b]  = lp;
                g_sel[b] = idx;
                g_avail[b * 16 + (idx >> 5)] &= ~(1u << (idx & 31));
                out[(size_t)b * NN * NN + (size_t)t * NN + idx] = 1.0f;
                if (t == NN - 1) out[(size_t)BB * NN * NN + b] = lp;
            }
        }
        gsync_grp(gid);
    }
}

// -------- host launcher: 2 graph nodes (memset + persistent kernel) --------
extern "C" void kernel_launch(void* const* d_in, const int* in_sizes, int n_in,
                              void* d_out, int out_size)
{
    int base = (n_in == 11) ? 1 : 0;   // batch_size scalar first per metadata
    const float* Wih0 = (const float*)d_in[base + 0];
    const float* Whh0 = (const float*)d_in[base + 1];
    const float* bih0 = (const float*)d_in[base + 2];
    const float* bhh0 = (const float*)d_in[base + 3];
    const float* Wih1 = (const float*)d_in[base + 4];
    const float* Whh1 = (const float*)d_in[base + 5];
    const float* bih1 = (const float*)d_in[base + 6];
    const float* bhh1 = (const float*)d_in[base + 7];
    const float* Wout = (const float*)d_in[base + 8];
    const float* bout = (const float*)d_in[base + 9];
    float* out = (float*)d_out;
    (void)in_sizes;

    size_t shbytes = (size_t)SMEMF * sizeof(float);   // 89088 B
    cudaFuncSetAttribute(perm_persistent,
                         cudaFuncAttributeMaxDynamicSharedMemorySize, (int)shbytes);

    cudaMemsetAsync(d_out, 0, (size_t)out_size * sizeof(float), 0);
    perm_persistent<<<GBLK, NTHR, shbytes>>>(Wih0, Whh0, bih0, bhh0,
                                             Wih1, Whh1, bih1, bhh1,
                                             Wout, bout, out);
}